// round 1
// baseline (speedup 1.0000x reference)
#include <cuda_runtime.h>
#include <cstdint>

#define PN 16384      // pixels per image (128*128)
#define HTOT 128
#define WTOT 128
#define NIMG 4

// ---------------- scratch (static device arrays; no allocs allowed) ----------
__device__ float g_pre[4 * 512 * 16384];   // pre-GN buffer (reused for conv1/conv2/conv3 outputs)
__device__ float g_cat[4 * 640 * 16384];   // [xd | branch0..3] concatenated channels
__device__ float g_y2 [4 * 128 * 16384];   // GN2 output

__constant__ int c_dils[4] = {1, 4, 8, 12};

// ---------------------------------------------------------------------------
// 1x1 conv as SGEMM:  Y[n][m][p] = sum_k A[m][k] * X[n][k][p]
// Block tile 128(M) x 128(P) x 8(K), 256 threads, 8x8 per thread.
// Requires M % 128 == 0, K % 8 == 0 (holds: M in {128,512}, K in {512,640,128}).
// ---------------------------------------------------------------------------
__global__ void __launch_bounds__(256) gemm_kernel(
    const float* __restrict__ A,   // M x K
    const float* __restrict__ X,   // per n: K x PN
    float* __restrict__ Y,         // per n: M x PN
    int M, int K)
{
    __shared__ float As[8][128];
    __shared__ float Bs[8][128];

    const int t  = threadIdx.x;
    const int n  = blockIdx.z;
    const int p0 = blockIdx.x * 128;
    const int m0 = blockIdx.y * 128;

    const float* Xn = X + (size_t)n * K * PN;
    float*       Yn = Y + (size_t)n * M * PN;

    const int tx = t & 15;        // 0..15  -> pixel micro-tile
    const int ty = t >> 4;        // 0..15  -> channel micro-tile
    const int ar = t >> 1;        // A tile row 0..127
    const int ac = (t & 1) * 4;   // A tile col (k) 0 or 4
    const int bk = t >> 5;        // B tile k 0..7
    const int bp = (t & 31) * 4;  // B tile p 0..124

    float acc[8][8];
#pragma unroll
    for (int i = 0; i < 8; i++)
#pragma unroll
        for (int j = 0; j < 8; j++) acc[i][j] = 0.f;

    const float* Aptr = A  + (size_t)(m0 + ar) * K + ac;
    const float* Bptr = Xn + (size_t)bk * PN + p0 + bp;

    for (int k0 = 0; k0 < K; k0 += 8) {
        float4 av = *(const float4*)(Aptr + k0);
        float4 bv = *(const float4*)(Bptr + (size_t)k0 * PN);
        __syncthreads();
        As[ac + 0][ar] = av.x;
        As[ac + 1][ar] = av.y;
        As[ac + 2][ar] = av.z;
        As[ac + 3][ar] = av.w;
        *(float4*)&Bs[bk][bp] = bv;
        __syncthreads();
#pragma unroll
        for (int kk = 0; kk < 8; kk++) {
            float a[8], b[8];
            *(float4*)&a[0] = *(const float4*)&As[kk][ty * 8];
            *(float4*)&a[4] = *(const float4*)&As[kk][ty * 8 + 4];
            *(float4*)&b[0] = *(const float4*)&Bs[kk][tx * 8];
            *(float4*)&b[4] = *(const float4*)&Bs[kk][tx * 8 + 4];
#pragma unroll
            for (int i = 0; i < 8; i++)
#pragma unroll
                for (int j = 0; j < 8; j++)
                    acc[i][j] = fmaf(a[i], b[j], acc[i][j]);
        }
    }

#pragma unroll
    for (int i = 0; i < 8; i++) {
        float* yp = Yn + (size_t)(m0 + ty * 8 + i) * PN + p0 + tx * 8;
        *(float4*)yp       = make_float4(acc[i][0], acc[i][1], acc[i][2], acc[i][3]);
        *(float4*)(yp + 4) = make_float4(acc[i][4], acc[i][5], acc[i][6], acc[i][7]);
    }
}

// ---------------------------------------------------------------------------
// GroupNorm + ReLU. One block per (group, n). Reduce then apply.
// in:  (n, Cin_tot, PN) at channel offset g*cpg
// out: (n, Cout_tot, PN) at channel offset cbase_out + g*cpg
// ---------------------------------------------------------------------------
__global__ void __launch_bounds__(256) gn_relu_kernel(
    const float* __restrict__ in, float* __restrict__ out,
    const float* __restrict__ gamma, const float* __restrict__ beta,
    int Cin_tot, int Cout_tot, int cbase_out, int cpg)
{
    const int g = blockIdx.x;
    const int n = blockIdx.y;
    const size_t bin  = ((size_t)n * Cin_tot  + (size_t)g * cpg) * PN;
    const size_t bout = ((size_t)n * Cout_tot + cbase_out + (size_t)g * cpg) * PN;
    const int cnt4 = cpg * PN / 4;

    const float4* in4 = (const float4*)(in + bin);
    float4*      out4 = (float4*)(out + bout);

    float s = 0.f, q = 0.f;
    for (int i = threadIdx.x; i < cnt4; i += 256) {
        float4 v = in4[i];
        s += v.x + v.y + v.z + v.w;
        q += v.x * v.x + v.y * v.y + v.z * v.z + v.w * v.w;
    }
    __shared__ float rs[256], rq[256];
    rs[threadIdx.x] = s;
    rq[threadIdx.x] = q;
    __syncthreads();
    for (int off = 128; off > 0; off >>= 1) {
        if (threadIdx.x < off) {
            rs[threadIdx.x] += rs[threadIdx.x + off];
            rq[threadIdx.x] += rq[threadIdx.x + off];
        }
        __syncthreads();
    }
    const float cntf = (float)(cpg * PN);
    const float mean = rs[0] / cntf;
    const float var  = rq[0] / cntf - mean * mean;
    const float inv  = rsqrtf(var + 1e-5f);

    for (int i = threadIdx.x; i < cnt4; i += 256) {
        int ch = g * cpg + (i >> 12);          // PN/4 = 4096 float4 per channel
        float sc = gamma[ch] * inv;
        float sh = beta[ch] - mean * sc;
        float4 v = in4[i];
        v.x = fmaxf(fmaf(v.x, sc, sh), 0.f);
        v.y = fmaxf(fmaf(v.y, sc, sh), 0.f);
        v.z = fmaxf(fmaf(v.z, sc, sh), 0.f);
        v.w = fmaxf(fmaf(v.w, sc, sh), 0.f);
        out4[i] = v;
    }
}

// ---------------------------------------------------------------------------
// Dynamic-filter branch:
//   logits[o] = conv3x3_dil_d(xd, w[o])   (9 output channels)
//   f = softmax_o(logits)
//   out[c]    = sum_o f[o] * shifted(xd[c], tap o)
// One block = 32x32 spatial tile, 256 threads, 4 px (2x2) per thread.
// grid.z = n*4 + branch. Reads xd = g_cat channels [0,128), writes
// g_cat channels [128*(1+branch), 128*(2+branch)).
// ---------------------------------------------------------------------------
__global__ void __launch_bounds__(256) branch_kernel(
    const float* __restrict__ wa, const float* __restrict__ wb,
    const float* __restrict__ wc, const float* __restrict__ wd)
{
    const int t = threadIdx.x;
    const int b = blockIdx.z & 3;
    const int n = blockIdx.z >> 2;
    const int d = c_dils[b];
    const float* wcat = (b == 0) ? wa : (b == 1) ? wb : (b == 2) ? wc : wd;

    const int px0 = blockIdx.x * 32;
    const int py0 = blockIdx.y * 32;
    const int WT  = 32 + 2 * d;       // halo tile width == height
    const int WTp = WT | 1;           // odd stride -> conflict-free strided taps

    __shared__ float tile[56 * 57];   // max: d=12 -> 56x57
    __shared__ float wsh[81];

    const int txi = t & 15, tyi = t >> 4;
    const int bx = txi * 2, by = tyi * 2;   // this thread's 2x2 pixel block
    const int lx = t & 63,  ly = t >> 6;    // loader lane (64 x 4)

    const float* xdbase = g_cat + (size_t)n * 640 * PN;   // channels 0..127

    float logit[9][4];
#pragma unroll
    for (int o = 0; o < 9; o++)
#pragma unroll
        for (int p = 0; p < 4; p++) logit[o][p] = 0.f;

    // ---- pass 1: conv logits over 128 channels ----
    for (int c = 0; c < 128; c++) {
        __syncthreads();
        if (lx < WT) {
            const int gx = px0 - d + lx;
            const bool xin = (gx >= 0) & (gx < WTOT);
            const float* src = xdbase + (size_t)c * PN;
            for (int y = ly; y < WT; y += 4) {
                int gy = py0 - d + y;
                float v = 0.f;
                if (xin && gy >= 0 && gy < HTOT) v = src[gy * WTOT + gx];
                tile[y * WTp + lx] = v;
            }
        }
        if (t < 81) wsh[t] = wcat[(size_t)(t / 9) * 128 * 9 + (size_t)c * 9 + (t % 9)];
        __syncthreads();

        float tap[4][9];
#pragma unroll
        for (int pi = 0; pi < 2; pi++)
#pragma unroll
            for (int pj = 0; pj < 2; pj++)
#pragma unroll
                for (int i = 0; i < 3; i++)
#pragma unroll
                    for (int j = 0; j < 3; j++)
                        tap[pi * 2 + pj][i * 3 + j] =
                            tile[(by + pi + i * d) * WTp + (bx + pj + j * d)];
#pragma unroll
        for (int o = 0; o < 9; o++) {
            float w[9];
#pragma unroll
            for (int k = 0; k < 9; k++) w[k] = wsh[o * 9 + k];
#pragma unroll
            for (int p = 0; p < 4; p++) {
                float acc = logit[o][p];
#pragma unroll
                for (int k = 0; k < 9; k++) acc = fmaf(w[k], tap[p][k], acc);
                logit[o][p] = acc;
            }
        }
    }

    // ---- softmax over 9 taps per pixel ----
    float f[4][9];
#pragma unroll
    for (int p = 0; p < 4; p++) {
        float m = logit[0][p];
#pragma unroll
        for (int o = 1; o < 9; o++) m = fmaxf(m, logit[o][p]);
        float s = 0.f;
#pragma unroll
        for (int o = 0; o < 9; o++) {
            float e = __expf(logit[o][p] - m);
            f[p][o] = e;
            s += e;
        }
        float r = 1.f / s;
#pragma unroll
        for (int o = 0; o < 9; o++) f[p][o] *= r;
    }

    // ---- pass 2: weighted 9-tap gather per channel ----
    const int cbase = 128 * (1 + b);
    for (int c = 0; c < 128; c++) {
        __syncthreads();
        if (lx < WT) {
            const int gx = px0 - d + lx;
            const bool xin = (gx >= 0) & (gx < WTOT);
            const float* src = xdbase + (size_t)c * PN;
            for (int y = ly; y < WT; y += 4) {
                int gy = py0 - d + y;
                float v = 0.f;
                if (xin && gy >= 0 && gy < HTOT) v = src[gy * WTOT + gx];
                tile[y * WTp + lx] = v;
            }
        }
        __syncthreads();

        float o0 = 0.f, o1 = 0.f, o2 = 0.f, o3 = 0.f;
#pragma unroll
        for (int i = 0; i < 3; i++)
#pragma unroll
            for (int j = 0; j < 3; j++) {
                int k = i * 3 + j;
                o0 = fmaf(tile[(by + 0 + i * d) * WTp + (bx + 0 + j * d)], f[0][k], o0);
                o1 = fmaf(tile[(by + 0 + i * d) * WTp + (bx + 1 + j * d)], f[1][k], o1);
                o2 = fmaf(tile[(by + 1 + i * d) * WTp + (bx + 0 + j * d)], f[2][k], o2);
                o3 = fmaf(tile[(by + 1 + i * d) * WTp + (bx + 1 + j * d)], f[3][k], o3);
            }

        float* dst = g_cat + ((size_t)n * 640 + cbase + c) * PN;
        const int gy0 = py0 + by, gx0 = px0 + bx;
        *(float2*)(dst + (size_t)gy0 * WTOT + gx0)       = make_float2(o0, o1);
        *(float2*)(dst + (size_t)(gy0 + 1) * WTOT + gx0) = make_float2(o2, o3);
    }
}

// ---------------------------------------------------------------------------
extern "C" void kernel_launch(void* const* d_in, const int* in_sizes, int n_in,
                              void* d_out, int out_size)
{
    const float* x   = (const float*)d_in[0];
    const float* w1  = (const float*)d_in[1];
    const float* g1g = (const float*)d_in[2];
    const float* g1b = (const float*)d_in[3];
    const float* wca = (const float*)d_in[4];
    const float* wcb = (const float*)d_in[5];
    const float* wcc = (const float*)d_in[6];
    const float* wcd = (const float*)d_in[7];
    const float* w2  = (const float*)d_in[8];
    const float* g2g = (const float*)d_in[9];
    const float* g2b = (const float*)d_in[10];
    const float* w3  = (const float*)d_in[11];
    const float* g3g = (const float*)d_in[12];
    const float* g3b = (const float*)d_in[13];
    float* out = (float*)d_out;

    float *pre, *cat, *y2;
    cudaGetSymbolAddress((void**)&pre, g_pre);
    cudaGetSymbolAddress((void**)&cat, g_cat);
    cudaGetSymbolAddress((void**)&y2,  g_y2);

    dim3 blk(256);

    // scale1: 1x1 conv (512->128) -> GN -> ReLU  (GN writes cat channels [0,128))
    gemm_kernel<<<dim3(128, 1, 4), blk>>>(w1, x, pre, 128, 512);
    gn_relu_kernel<<<dim3(32, 4), blk>>>(pre, cat, g1g, g1b, 128, 640, 0, 4);

    // four dilated dynamic-filter branches -> cat channels [128,640)
    branch_kernel<<<dim3(4, 4, 16), blk>>>(wca, wcb, wcc, wcd);

    // scale2: 1x1 conv (640->128) -> GN -> ReLU
    gemm_kernel<<<dim3(128, 1, 4), blk>>>(w2, cat, pre, 128, 640);
    gn_relu_kernel<<<dim3(32, 4), blk>>>(pre, y2, g2g, g2b, 128, 128, 0, 4);

    // scale3: 1x1 conv (128->512) -> GN -> ReLU -> d_out
    gemm_kernel<<<dim3(128, 4, 4), blk>>>(w3, y2, pre, 512, 128);
    gn_relu_kernel<<<dim3(32, 4), blk>>>(pre, out, g3g, g3b, 512, 512, 0, 16);
}

// round 2
// speedup vs baseline: 1.6058x; 1.6058x over previous
#include <cuda_runtime.h>
#include <cstdint>

#define PN 16384      // pixels per image (128*128)
#define HTOT 128
#define WTOT 128
#define NIMG 4

// ---------------- scratch (static device arrays; no allocs allowed) ----------
__device__ float g_pre[4 * 512 * 16384];   // pre-GN buffer (reused for conv1/conv2/conv3 outputs)
__device__ float g_cat[4 * 640 * 16384];   // [xd | branch0..3] concatenated channels
__device__ float g_y2 [4 * 128 * 16384];   // GN2 output

__constant__ int c_dils[4] = {1, 4, 8, 12};

// ---------------------------------------------------------------------------
// tf32 tensor-core SGEMM for 1x1 conv:  Y[n][m][p] = sum_k A[m][k] * X[n][k][p]
// Block tile 128(M) x 128(P) x 16(K), 256 threads = 8 warps (2M x 4N),
// warp tile 64x32 via m16n8k8 tf32 mma.sync. cp.async double-buffered.
// Requires M%128==0, K%16==0 (holds: M in {128,512}, K in {512,640,128}).
// ---------------------------------------------------------------------------
#define AS_STR 20          // A smem row stride (floats): banks 4g+tg conflict-free
#define BS_STR 136         // B smem row stride (floats): banks 8tg+g conflict-free
#define AS_SZ  (128 * AS_STR)
#define BS_SZ  (16 * BS_STR)

#define CP16(dst_u32, src_ptr) \
    asm volatile("cp.async.cg.shared.global [%0], [%1], 16;\n" :: "r"(dst_u32), "l"(src_ptr))

#define MMA_TF32(c, a, b)                                                      \
    asm volatile(                                                              \
        "mma.sync.aligned.m16n8k8.row.col.f32.tf32.tf32.f32 "                  \
        "{%0,%1,%2,%3}, {%4,%5,%6,%7}, {%8,%9}, {%0,%1,%2,%3};"                \
        : "+f"((c)[0]), "+f"((c)[1]), "+f"((c)[2]), "+f"((c)[3])               \
        : "r"((a)[0]), "r"((a)[1]), "r"((a)[2]), "r"((a)[3]),                  \
          "r"((b)[0]), "r"((b)[1]))

__global__ void __launch_bounds__(256, 2) gemm_tf32_kernel(
    const float* __restrict__ A,   // M x K
    const float* __restrict__ X,   // per n: K x PN
    float* __restrict__ Y,         // per n: M x PN
    int M, int K)
{
    __shared__ float As[2][AS_SZ];
    __shared__ float Bs[2][BS_SZ];

    const int t  = threadIdx.x;
    const int n  = blockIdx.z;
    const int p0 = blockIdx.x * 128;
    const int m0 = blockIdx.y * 128;

    const float* Xn = X + (size_t)n * K * PN;
    float*       Yn = Y + (size_t)n * M * PN;

    const int warp = t >> 5;
    const int lane = t & 31;
    const int wm = warp & 1;          // 0..1  (64-row slabs)
    const int wn = warp >> 1;         // 0..3  (32-col slabs)
    const int g  = lane >> 2;         // 0..7
    const int tg = lane & 3;          // 0..3

    const uint32_t as_base = (uint32_t)__cvta_generic_to_shared(&As[0][0]);
    const uint32_t bs_base = (uint32_t)__cvta_generic_to_shared(&Bs[0][0]);

    float acc[4][4][4];
#pragma unroll
    for (int i = 0; i < 4; i++)
#pragma unroll
        for (int j = 0; j < 4; j++)
#pragma unroll
            for (int r = 0; r < 4; r++) acc[i][j][r] = 0.f;

    const int nk = K >> 4;

    // ---- async stage loader: A 128x16, B 16x128 (512 x 16B chunks each) ----
    auto issue_stage = [&](int bufi, int k0) {
#pragma unroll
        for (int i = 0; i < 2; i++) {
            int c   = t + i * 256;
            int row = c >> 2;
            int kc  = (c & 3) * 4;
            uint32_t dst = as_base + (uint32_t)(bufi * AS_SZ + row * AS_STR + kc) * 4u;
            const float* src = A + (size_t)(m0 + row) * K + k0 + kc;
            CP16(dst, src);
        }
#pragma unroll
        for (int i = 0; i < 2; i++) {
            int c   = t + i * 256;
            int row = c >> 5;
            int pc  = (c & 31) * 4;
            uint32_t dst = bs_base + (uint32_t)(bufi * BS_SZ + row * BS_STR + pc) * 4u;
            const float* src = Xn + (size_t)(k0 + row) * PN + p0 + pc;
            CP16(dst, src);
        }
    };

    issue_stage(0, 0);
    asm volatile("cp.async.commit_group;\n" ::: "memory");

    int buf = 0;
    for (int kt = 0; kt < nk; kt++) {
        if (kt + 1 < nk) {
            issue_stage(buf ^ 1, (kt + 1) * 16);
            asm volatile("cp.async.commit_group;\n" ::: "memory");
            asm volatile("cp.async.wait_group 1;\n" ::: "memory");
        } else {
            asm volatile("cp.async.wait_group 0;\n" ::: "memory");
        }
        __syncthreads();

        const float* as = &As[buf][0];
        const float* bs = &Bs[buf][0];
#pragma unroll
        for (int ks = 0; ks < 16; ks += 8) {
            uint32_t af[4][4], bf[4][2];
#pragma unroll
            for (int i = 0; i < 4; i++) {
                int mb = wm * 64 + i * 16;
                af[i][0] = __float_as_uint(as[(mb + g)     * AS_STR + ks + tg]);
                af[i][1] = __float_as_uint(as[(mb + g + 8) * AS_STR + ks + tg]);
                af[i][2] = __float_as_uint(as[(mb + g)     * AS_STR + ks + tg + 4]);
                af[i][3] = __float_as_uint(as[(mb + g + 8) * AS_STR + ks + tg + 4]);
            }
#pragma unroll
            for (int j = 0; j < 4; j++) {
                int nb = wn * 32 + j * 8;
                bf[j][0] = __float_as_uint(bs[(ks + tg)     * BS_STR + nb + g]);
                bf[j][1] = __float_as_uint(bs[(ks + tg + 4) * BS_STR + nb + g]);
            }
#pragma unroll
            for (int i = 0; i < 4; i++)
#pragma unroll
                for (int j = 0; j < 4; j++)
                    MMA_TF32(acc[i][j], af[i], bf[j]);
        }
        __syncthreads();
        buf ^= 1;
    }

    // ---- epilogue: direct float2 stores (fills full 32B sectors per row) ----
#pragma unroll
    for (int i = 0; i < 4; i++) {
        int mrow = m0 + wm * 64 + i * 16 + g;
#pragma unroll
        for (int j = 0; j < 4; j++) {
            int col = p0 + wn * 32 + j * 8 + 2 * tg;
            *(float2*)(Yn + (size_t)mrow * PN + col)       = make_float2(acc[i][j][0], acc[i][j][1]);
            *(float2*)(Yn + (size_t)(mrow + 8) * PN + col) = make_float2(acc[i][j][2], acc[i][j][3]);
        }
    }
}

// ---------------------------------------------------------------------------
// GroupNorm + ReLU. One block per (group, n). Reduce then apply.
// ---------------------------------------------------------------------------
__global__ void __launch_bounds__(256) gn_relu_kernel(
    const float* __restrict__ in, float* __restrict__ out,
    const float* __restrict__ gamma, const float* __restrict__ beta,
    int Cin_tot, int Cout_tot, int cbase_out, int cpg)
{
    const int g = blockIdx.x;
    const int n = blockIdx.y;
    const size_t bin  = ((size_t)n * Cin_tot  + (size_t)g * cpg) * PN;
    const size_t bout = ((size_t)n * Cout_tot + cbase_out + (size_t)g * cpg) * PN;
    const int cnt4 = cpg * PN / 4;

    const float4* in4 = (const float4*)(in + bin);
    float4*      out4 = (float4*)(out + bout);

    float s = 0.f, q = 0.f;
    for (int i = threadIdx.x; i < cnt4; i += 256) {
        float4 v = in4[i];
        s += v.x + v.y + v.z + v.w;
        q += v.x * v.x + v.y * v.y + v.z * v.z + v.w * v.w;
    }
    __shared__ float rs[256], rq[256];
    rs[threadIdx.x] = s;
    rq[threadIdx.x] = q;
    __syncthreads();
    for (int off = 128; off > 0; off >>= 1) {
        if (threadIdx.x < off) {
            rs[threadIdx.x] += rs[threadIdx.x + off];
            rq[threadIdx.x] += rq[threadIdx.x + off];
        }
        __syncthreads();
    }
    const float cntf = (float)(cpg * PN);
    const float mean = rs[0] / cntf;
    const float var  = rq[0] / cntf - mean * mean;
    const float inv  = rsqrtf(var + 1e-5f);

    for (int i = threadIdx.x; i < cnt4; i += 256) {
        int ch = g * cpg + (i >> 12);          // PN/4 = 4096 float4 per channel
        float sc = gamma[ch] * inv;
        float sh = beta[ch] - mean * sc;
        float4 v = in4[i];
        v.x = fmaxf(fmaf(v.x, sc, sh), 0.f);
        v.y = fmaxf(fmaf(v.y, sc, sh), 0.f);
        v.z = fmaxf(fmaf(v.z, sc, sh), 0.f);
        v.w = fmaxf(fmaf(v.w, sc, sh), 0.f);
        out4[i] = v;
    }
}

// ---------------------------------------------------------------------------
// Dynamic-filter branch (unchanged from R1): conv3x3 logits -> softmax ->
// 9-tap weighted gather. One block = 32x32 tile, 256 threads, 4 px/thread.
// ---------------------------------------------------------------------------
__global__ void __launch_bounds__(256) branch_kernel(
    const float* __restrict__ wa, const float* __restrict__ wb,
    const float* __restrict__ wc, const float* __restrict__ wd)
{
    const int t = threadIdx.x;
    const int b = blockIdx.z & 3;
    const int n = blockIdx.z >> 2;
    const int d = c_dils[b];
    const float* wcat = (b == 0) ? wa : (b == 1) ? wb : (b == 2) ? wc : wd;

    const int px0 = blockIdx.x * 32;
    const int py0 = blockIdx.y * 32;
    const int WT  = 32 + 2 * d;
    const int WTp = WT | 1;

    __shared__ float tile[56 * 57];
    __shared__ float wsh[81];

    const int txi = t & 15, tyi = t >> 4;
    const int bx = txi * 2, by = tyi * 2;
    const int lx = t & 63,  ly = t >> 6;

    const float* xdbase = g_cat + (size_t)n * 640 * PN;

    float logit[9][4];
#pragma unroll
    for (int o = 0; o < 9; o++)
#pragma unroll
        for (int p = 0; p < 4; p++) logit[o][p] = 0.f;

    for (int c = 0; c < 128; c++) {
        __syncthreads();
        if (lx < WT) {
            const int gx = px0 - d + lx;
            const bool xin = (gx >= 0) & (gx < WTOT);
            const float* src = xdbase + (size_t)c * PN;
            for (int y = ly; y < WT; y += 4) {
                int gy = py0 - d + y;
                float v = 0.f;
                if (xin && gy >= 0 && gy < HTOT) v = src[gy * WTOT + gx];
                tile[y * WTp + lx] = v;
            }
        }
        if (t < 81) wsh[t] = wcat[(size_t)(t / 9) * 128 * 9 + (size_t)c * 9 + (t % 9)];
        __syncthreads();

        float tap[4][9];
#pragma unroll
        for (int pi = 0; pi < 2; pi++)
#pragma unroll
            for (int pj = 0; pj < 2; pj++)
#pragma unroll
                for (int i = 0; i < 3; i++)
#pragma unroll
                    for (int j = 0; j < 3; j++)
                        tap[pi * 2 + pj][i * 3 + j] =
                            tile[(by + pi + i * d) * WTp + (bx + pj + j * d)];
#pragma unroll
        for (int o = 0; o < 9; o++) {
            float w[9];
#pragma unroll
            for (int k = 0; k < 9; k++) w[k] = wsh[o * 9 + k];
#pragma unroll
            for (int p = 0; p < 4; p++) {
                float acc = logit[o][p];
#pragma unroll
                for (int k = 0; k < 9; k++) acc = fmaf(w[k], tap[p][k], acc);
                logit[o][p] = acc;
            }
        }
    }

    float f[4][9];
#pragma unroll
    for (int p = 0; p < 4; p++) {
        float m = logit[0][p];
#pragma unroll
        for (int o = 1; o < 9; o++) m = fmaxf(m, logit[o][p]);
        float s = 0.f;
#pragma unroll
        for (int o = 0; o < 9; o++) {
            float e = __expf(logit[o][p] - m);
            f[p][o] = e;
            s += e;
        }
        float r = 1.f / s;
#pragma unroll
        for (int o = 0; o < 9; o++) f[p][o] *= r;
    }

    const int cbase = 128 * (1 + b);
    for (int c = 0; c < 128; c++) {
        __syncthreads();
        if (lx < WT) {
            const int gx = px0 - d + lx;
            const bool xin = (gx >= 0) & (gx < WTOT);
            const float* src = xdbase + (size_t)c * PN;
            for (int y = ly; y < WT; y += 4) {
                int gy = py0 - d + y;
                float v = 0.f;
                if (xin && gy >= 0 && gy < HTOT) v = src[gy * WTOT + gx];
                tile[y * WTp + lx] = v;
            }
        }
        __syncthreads();

        float o0 = 0.f, o1 = 0.f, o2 = 0.f, o3 = 0.f;
#pragma unroll
        for (int i = 0; i < 3; i++)
#pragma unroll
            for (int j = 0; j < 3; j++) {
                int k = i * 3 + j;
                o0 = fmaf(tile[(by + 0 + i * d) * WTp + (bx + 0 + j * d)], f[0][k], o0);
                o1 = fmaf(tile[(by + 0 + i * d) * WTp + (bx + 1 + j * d)], f[1][k], o1);
                o2 = fmaf(tile[(by + 1 + i * d) * WTp + (bx + 0 + j * d)], f[2][k], o2);
                o3 = fmaf(tile[(by + 1 + i * d) * WTp + (bx + 1 + j * d)], f[3][k], o3);
            }

        float* dst = g_cat + ((size_t)n * 640 + cbase + c) * PN;
        const int gy0 = py0 + by, gx0 = px0 + bx;
        *(float2*)(dst + (size_t)gy0 * WTOT + gx0)       = make_float2(o0, o1);
        *(float2*)(dst + (size_t)(gy0 + 1) * WTOT + gx0) = make_float2(o2, o3);
    }
}

// ---------------------------------------------------------------------------
extern "C" void kernel_launch(void* const* d_in, const int* in_sizes, int n_in,
                              void* d_out, int out_size)
{
    const float* x   = (const float*)d_in[0];
    const float* w1  = (const float*)d_in[1];
    const float* g1g = (const float*)d_in[2];
    const float* g1b = (const float*)d_in[3];
    const float* wca = (const float*)d_in[4];
    const float* wcb = (const float*)d_in[5];
    const float* wcc = (const float*)d_in[6];
    const float* wcd = (const float*)d_in[7];
    const float* w2  = (const float*)d_in[8];
    const float* g2g = (const float*)d_in[9];
    const float* g2b = (const float*)d_in[10];
    const float* w3  = (const float*)d_in[11];
    const float* g3g = (const float*)d_in[12];
    const float* g3b = (const float*)d_in[13];
    float* out = (float*)d_out;

    float *pre, *cat, *y2;
    cudaGetSymbolAddress((void**)&pre, g_pre);
    cudaGetSymbolAddress((void**)&cat, g_cat);
    cudaGetSymbolAddress((void**)&y2,  g_y2);

    dim3 blk(256);

    // scale1: 1x1 conv (512->128) -> GN -> ReLU  (GN writes cat channels [0,128))
    gemm_tf32_kernel<<<dim3(128, 1, 4), blk>>>(w1, x, pre, 128, 512);
    gn_relu_kernel<<<dim3(32, 4), blk>>>(pre, cat, g1g, g1b, 128, 640, 0, 4);

    // four dilated dynamic-filter branches -> cat channels [128,640)
    branch_kernel<<<dim3(4, 4, 16), blk>>>(wca, wcb, wcc, wcd);

    // scale2: 1x1 conv (640->128) -> GN -> ReLU
    gemm_tf32_kernel<<<dim3(128, 1, 4), blk>>>(w2, cat, pre, 128, 640);
    gn_relu_kernel<<<dim3(32, 4), blk>>>(pre, y2, g2g, g2b, 128, 128, 0, 4);

    // scale3: 1x1 conv (128->512) -> GN -> ReLU -> d_out
    gemm_tf32_kernel<<<dim3(128, 4, 4), blk>>>(w3, y2, pre, 512, 128);
    gn_relu_kernel<<<dim3(32, 4), blk>>>(pre, out, g3g, g3b, 512, 512, 0, 16);
}